// round 11
// baseline (speedup 1.0000x reference)
#include <cuda_runtime.h>

// ---------------------------------------------------------------------------
// MSELoss: out[0] = mean((yhat - y)^2) over 16384 x 4096 fp32 (512 MiB read).
// R11: blocked contiguous partitioning. Each of 2048 CTAs owns a contiguous
// 128 KiB chunk of each input (8192 float4); threads stride by 256 within it.
// Fully coalesced (warp = 16 consecutive 128B lines per iteration). Improves
// per-SM DRAM page / L2-window locality vs interleaved grid-stride; worst
// case ties (LTS cap is pattern-independent on B300).
// Fused deterministic last-block-done finalization, self-resetting counter.
// ---------------------------------------------------------------------------

#define NBLK 2048
#define NTHR 256

__device__ float        g_partials[NBLK];
__device__ unsigned int g_done_count = 0;

__device__ __forceinline__ float block_reduce(float acc, float* warp_sums)
{
    #pragma unroll
    for (int off = 16; off > 0; off >>= 1)
        acc += __shfl_xor_sync(0xFFFFFFFFu, acc, off);

    int lane = threadIdx.x & 31;
    int wid  = threadIdx.x >> 5;
    if (lane == 0) warp_sums[wid] = acc;
    __syncthreads();

    float v = 0.0f;
    if (wid == 0) {
        v = (lane < NTHR / 32) ? warp_sums[lane] : 0.0f;
        #pragma unroll
        for (int off = 16; off > 0; off >>= 1)
            v += __shfl_xor_sync(0xFFFFFFFFu, v, off);
    }
    return v;  // valid in warp 0 lane 0
}

__global__ __launch_bounds__(NTHR) void mse_kernel(
    const float* __restrict__ yhat,
    const float* __restrict__ y,
    float* __restrict__ out,
    long long n4, float inv_n)
{
    const float4* __restrict__ a4 = reinterpret_cast<const float4*>(yhat);
    const float4* __restrict__ b4 = reinterpret_cast<const float4*>(y);

    // Blocked partition: CTA b owns [b*chunk, (b+1)*chunk) float4 elements.
    // n4 = 16777216 = 2048 * 8192, so chunk = 8192 exactly (no remainder for
    // this problem; guarded loop keeps generality).
    long long chunk = (n4 + NBLK - 1) / NBLK;
    long long base  = (long long)blockIdx.x * chunk;
    long long end   = base + chunk;
    if (end > n4) end = n4;

    float acc = 0.0f;
    for (long long i = base + threadIdx.x; i < end; i += NTHR) {
        float4 a = a4[i];
        float4 b = b4[i];
        float d0 = a.x - b.x;
        float d1 = a.y - b.y;
        float d2 = a.z - b.z;
        float d3 = a.w - b.w;
        acc = fmaf(d0, d0, acc);
        acc = fmaf(d1, d1, acc);
        acc = fmaf(d2, d2, acc);
        acc = fmaf(d3, d3, acc);
    }

    __shared__ float warp_sums[NTHR / 32];
    float bsum = block_reduce(acc, warp_sums);
    if (threadIdx.x == 0) g_partials[blockIdx.x] = bsum;

    // Fused finalization: last CTA to finish reduces all partials in a
    // fixed order (deterministic). Counter self-resets for graph replay.
    __shared__ bool s_last;
    __threadfence();
    if (threadIdx.x == 0) {
        unsigned int prev = atomicAdd(&g_done_count, 1u);
        s_last = (prev == NBLK - 1);
    }
    __syncthreads();

    if (s_last) {
        // 2048 partials / 256 threads = 8 each, fixed order => deterministic.
        float facc = 0.0f;
        #pragma unroll
        for (int k = 0; k < NBLK / NTHR; k++)
            facc += g_partials[threadIdx.x + k * NTHR];

        __syncthreads();  // warp_sums reuse
        float fsum = block_reduce(facc, warp_sums);
        if (threadIdx.x == 0) {
            out[0] = fsum * inv_n;
            g_done_count = 0;  // reset for next graph replay
        }
    }
}

extern "C" void kernel_launch(void* const* d_in, const int* in_sizes, int n_in,
                              void* d_out, int out_size)
{
    const float* yhat = (const float*)d_in[0];
    const float* y    = (const float*)d_in[1];
    float* out        = (float*)d_out;

    long long n  = (long long)in_sizes[0];  // 67108864, divisible by 4
    long long n4 = n / 4;

    mse_kernel<<<NBLK, NTHR>>>(yhat, y, out, n4, 1.0f / (float)n);
}

// round 12
// speedup vs baseline: 1.0531x; 1.0531x over previous
#include <cuda_runtime.h>

// ---------------------------------------------------------------------------
// MSELoss: out[0] = mean((yhat - y)^2) over 16384 x 4096 fp32 (512 MiB read).
// FINAL champion (reproduced 3x at 80.35-80.4 us wall, 84.7-85.3% DRAM,
// 6.7-6.8 TB/s ~ B300 practical streaming ceiling):
//   - 2048 CTAs x 256 threads, plain compiler-scheduled float4 interleaved
//     grid-stride loop (32 regs, occ ~93%).
//   - Fused deterministic last-block-done finalization: fixed-order partial
//     reduction (no float atomics), single launch, counter self-resets for
//     CUDA-graph replay.
//
// Exhaustively probed and rejected with measurements:
//   - manual 4-stride unroll         90.1 us (wrecked scheduling/pattern)
//   - __ldcs streaming loads         83.4 us (+6 regs, occ 95.6 -> 71.9)
//   - blocked contiguous chunks      84.4 us (+6 regs, occ 91 -> 70)
//   - grid 1024x256                  imbalance (occ 69%)
//   - grid 1184 full wave            80.6 us, DRAM -2.6% (neutral)
//   - 1024x512 same thread count     80.6 us (tie)
//   - 8192x256 fine granularity      80.6 us (tie/worse profiled)
// Every reg-allocation perturbation of the loop body loses; every shape
// plateaus at ~85% of spec => machine streaming ceiling reached.
// ---------------------------------------------------------------------------

#define NBLK 2048
#define NTHR 256

__device__ float        g_partials[NBLK];
__device__ unsigned int g_done_count = 0;

__device__ __forceinline__ float block_reduce(float acc, float* warp_sums)
{
    #pragma unroll
    for (int off = 16; off > 0; off >>= 1)
        acc += __shfl_xor_sync(0xFFFFFFFFu, acc, off);

    int lane = threadIdx.x & 31;
    int wid  = threadIdx.x >> 5;
    if (lane == 0) warp_sums[wid] = acc;
    __syncthreads();

    float v = 0.0f;
    if (wid == 0) {
        v = (lane < NTHR / 32) ? warp_sums[lane] : 0.0f;
        #pragma unroll
        for (int off = 16; off > 0; off >>= 1)
            v += __shfl_xor_sync(0xFFFFFFFFu, v, off);
    }
    return v;  // valid in warp 0 lane 0
}

__global__ __launch_bounds__(NTHR) void mse_kernel(
    const float* __restrict__ yhat,
    const float* __restrict__ y,
    float* __restrict__ out,
    long long n4, float inv_n)
{
    const float4* __restrict__ a4 = reinterpret_cast<const float4*>(yhat);
    const float4* __restrict__ b4 = reinterpret_cast<const float4*>(y);

    // Plain interleaved grid-stride loop, compiler-scheduled (best shape).
    float acc = 0.0f;
    long long stride = (long long)gridDim.x * blockDim.x;
    for (long long i = (long long)blockIdx.x * blockDim.x + threadIdx.x;
         i < n4; i += stride) {
        float4 a = a4[i];
        float4 b = b4[i];
        float d0 = a.x - b.x;
        float d1 = a.y - b.y;
        float d2 = a.z - b.z;
        float d3 = a.w - b.w;
        acc = fmaf(d0, d0, acc);
        acc = fmaf(d1, d1, acc);
        acc = fmaf(d2, d2, acc);
        acc = fmaf(d3, d3, acc);
    }

    __shared__ float warp_sums[NTHR / 32];
    float bsum = block_reduce(acc, warp_sums);
    if (threadIdx.x == 0) g_partials[blockIdx.x] = bsum;

    // Fused finalization: last CTA to finish reduces all partials in a
    // fixed order (deterministic). Counter self-resets for graph replay.
    __shared__ bool s_last;
    __threadfence();
    if (threadIdx.x == 0) {
        unsigned int prev = atomicAdd(&g_done_count, 1u);
        s_last = (prev == NBLK - 1);
    }
    __syncthreads();

    if (s_last) {
        // 2048 partials / 256 threads = 8 each, fixed order => deterministic.
        float facc = 0.0f;
        #pragma unroll
        for (int k = 0; k < NBLK / NTHR; k++)
            facc += g_partials[threadIdx.x + k * NTHR];

        __syncthreads();  // warp_sums reuse
        float fsum = block_reduce(facc, warp_sums);
        if (threadIdx.x == 0) {
            out[0] = fsum * inv_n;
            g_done_count = 0;  // reset for next graph replay
        }
    }
}

extern "C" void kernel_launch(void* const* d_in, const int* in_sizes, int n_in,
                              void* d_out, int out_size)
{
    const float* yhat = (const float*)d_in[0];
    const float* y    = (const float*)d_in[1];
    float* out        = (float*)d_out;

    long long n  = (long long)in_sizes[0];  // 67108864, divisible by 4
    long long n4 = n / 4;

    mse_kernel<<<NBLK, NTHR>>>(yhat, y, out, n4, 1.0f / (float)n);
}